// round 4
// baseline (speedup 1.0000x reference)
#include <cuda_runtime.h>
#include <cuda_bf16.h>

#define NMAX 100000
#define EMAX 1600000
#define DIM  128

__device__ int   g_deg[NMAX];
__device__ int   g_fill[NMAX];
__device__ int   g_rowptr[NMAX + 1];
__device__ int   g_srcidx[EMAX];
__device__ float g_dis[NMAX];
__device__ float g_bufA[(size_t)NMAX * DIM];
__device__ float g_bufB[(size_t)NMAX * DIM];
__device__ float g_Wp[4][64 * DIM * 2];

__device__ __forceinline__ unsigned long long fma2(unsigned long long a,
                                                   unsigned long long b,
                                                   unsigned long long c) {
    unsigned long long d;
    asm("fma.rn.f32x2 %0, %1, %2, %3;" : "=l"(d) : "l"(a), "l"(b), "l"(c));
    return d;
}
__device__ __forceinline__ float hsum2(unsigned long long v) {
    float lo, hi;
    asm("mov.b64 {%0, %1}, %2;" : "=f"(lo), "=f"(hi) : "l"(v));
    return lo + hi;
}

__global__ void k_zero(int n) {
    int i = blockIdx.x * blockDim.x + threadIdx.x;
    if (i < n) { g_deg[i] = 0; g_fill[i] = 0; }
}

__global__ void k_hist(const int* __restrict__ dst, int E) {
    int i = blockIdx.x * blockDim.x + threadIdx.x;
    if (i < E) atomicAdd(&g_deg[dst[i]], 1);
}

__global__ void k_scan(int n, int E) {
    __shared__ int carry;
    __shared__ int wsum[32];
    int tid = threadIdx.x;
    if (tid == 0) carry = 0;
    __syncthreads();
    for (int base = 0; base < n; base += 1024) {
        int i = base + tid;
        int v = (i < n) ? g_deg[i] : 0;
        int x = v;
        #pragma unroll
        for (int o = 1; o < 32; o <<= 1) {
            int y = __shfl_up_sync(0xffffffffu, x, o);
            if ((tid & 31) >= o) x += y;
        }
        if ((tid & 31) == 31) wsum[tid >> 5] = x;
        __syncthreads();
        if (tid < 32) {
            int s = wsum[tid];
            #pragma unroll
            for (int o = 1; o < 32; o <<= 1) {
                int y = __shfl_up_sync(0xffffffffu, s, o);
                if (tid >= o) s += y;
            }
            wsum[tid] = s;
        }
        __syncthreads();
        int pre = carry + x - v + ((tid >= 32) ? wsum[(tid >> 5) - 1] : 0);
        if (i < n) {
            g_rowptr[i] = pre;
            g_dis[i] = rsqrtf((float)(v + 1));
        }
        int tot = wsum[31];
        __syncthreads();
        if (tid == 0) carry += tot;
        __syncthreads();
    }
    if (tid == 0) g_rowptr[n] = E;
}

__global__ void k_fill(const int* __restrict__ src, const int* __restrict__ dst, int E) {
    int i = blockIdx.x * blockDim.x + threadIdx.x;
    if (i < E) {
        int d = dst[i];
        int pos = g_rowptr[d] + atomicAdd(&g_fill[d], 1);
        g_srcidx[pos] = src[i];
    }
}

__global__ void k_packW(const float* __restrict__ W, float* __restrict__ Wp) {
    int i = blockIdx.x * blockDim.x + threadIdx.x;
    if (i < 64 * DIM) {
        int p = i >> 7, c = i & 127;
        Wp[i * 2]     = W[(2 * p) * DIM + c];
        Wp[i * 2 + 1] = W[(2 * p + 1) * DIM + c];
    }
}

// mode 0: C = (A@W) * g_dis[row] ; mode 1: C = elu(A@W + bias)
__global__ __launch_bounds__(256) void k_gemm(
    const float* __restrict__ A, const float* __restrict__ Wp,
    const float* __restrict__ bias,
    float* __restrict__ C, int n, int mode)
{
    int tx = threadIdx.x & 31;
    int ty = threadIdx.x >> 5;
    int row0 = blockIdx.x * 64 + ty * 8;

    int ridx[8];
    #pragma unroll
    for (int r = 0; r < 8; r++) {
        int rr = row0 + r;
        ridx[r] = (rr < n) ? rr : (n - 1);
    }

    unsigned long long acc[8][4];
    #pragma unroll
    for (int r = 0; r < 8; r++)
        #pragma unroll
        for (int c = 0; c < 4; c++) acc[r][c] = 0ull;

    #pragma unroll 4
    for (int k0 = 0; k0 < DIM; k0 += 4) {
        ulonglong2 a[8];
        #pragma unroll
        for (int r = 0; r < 8; r++)
            a[r] = __ldg((const ulonglong2*)(A + (size_t)ridx[r] * DIM + k0));

        #pragma unroll
        for (int half = 0; half < 2; half++) {
            int p = (k0 >> 1) + half;
            const ulonglong2* wp = (const ulonglong2*)(Wp + p * 256 + tx * 8);
            ulonglong2 w01 = __ldg(wp);
            ulonglong2 w23 = __ldg(wp + 1);
            #pragma unroll
            for (int r = 0; r < 8; r++) {
                unsigned long long av = half ? a[r].y : a[r].x;
                acc[r][0] = fma2(av, w01.x, acc[r][0]);
                acc[r][1] = fma2(av, w01.y, acc[r][1]);
                acc[r][2] = fma2(av, w23.x, acc[r][2]);
                acc[r][3] = fma2(av, w23.y, acc[r][3]);
            }
        }
    }

    #pragma unroll
    for (int r = 0; r < 8; r++) {
        int row = row0 + r;
        if (row >= n) break;
        float4 o;
        o.x = hsum2(acc[r][0]);
        o.y = hsum2(acc[r][1]);
        o.z = hsum2(acc[r][2]);
        o.w = hsum2(acc[r][3]);
        if (mode == 0) {
            float s = __ldg(&g_dis[row]);
            o.x *= s; o.y *= s; o.z *= s; o.w *= s;
        } else {
            float4 b = __ldg(((const float4*)bias) + tx);
            o.x += b.x; o.y += b.y; o.z += b.z; o.w += b.w;
            o.x = (o.x > 0.f) ? o.x : expm1f(o.x);
            o.y = (o.y > 0.f) ? o.y : expm1f(o.y);
            o.z = (o.z > 0.f) ? o.z : expm1f(o.z);
            o.w = (o.w > 0.f) ? o.w : expm1f(o.w);
        }
        ((float4*)C)[(size_t)row * 32 + tx] = o;
    }
}

__global__ __launch_bounds__(256) void k_agg(
    const float* __restrict__ g, const float* __restrict__ bias,
    float* __restrict__ out, int n)
{
    int lane = threadIdx.x & 31;
    int w = threadIdx.x >> 5;
    int v = blockIdx.x * 8 + w;
    if (v >= n) return;

    const float4* g4 = (const float4*)g;
    float4 acc = __ldg(&g4[(size_t)v * 32 + lane]);

    int beg = __ldg(&g_rowptr[v]);
    int end = __ldg(&g_rowptr[v + 1]);
    for (int e0 = beg; e0 < end; e0 += 32) {
        int cnt = end - e0;
        if (cnt > 32) cnt = 32;
        int s = (lane < cnt) ? __ldg(&g_srcidx[e0 + lane]) : 0;
        for (int j = 0; j < cnt; j++) {
            int sj = __shfl_sync(0xffffffffu, s, j);
            float4 gv = __ldg(&g4[(size_t)sj * 32 + lane]);
            acc.x += gv.x; acc.y += gv.y; acc.z += gv.z; acc.w += gv.w;
        }
    }

    float ds = __ldg(&g_dis[v]);
    float4 b = __ldg(((const float4*)bias) + lane);
    float4 o;
    o.x = fmaxf(fmaf(acc.x, ds, b.x), 0.f);
    o.y = fmaxf(fmaf(acc.y, ds, b.y), 0.f);
    o.z = fmaxf(fmaf(acc.z, ds, b.z), 0.f);
    o.w = fmaxf(fmaf(acc.w, ds, b.w), 0.f);
    ((float4*)out)[(size_t)v * 32 + lane] = o;
}

__global__ __launch_bounds__(256) void k_mlp2(
    const float* __restrict__ M, const float* __restrict__ W,
    const float* __restrict__ b, float* __restrict__ logits,
    float* __restrict__ probs, int n)
{
    __shared__ float Ws[DIM * 40];
    for (int i = threadIdx.x; i < DIM * 40; i += 256) Ws[i] = W[i];
    __syncthreads();

    int rl = threadIdx.x >> 3;
    int jg = threadIdx.x & 7;
    int row = blockIdx.x * 32 + rl;
    int rowc = (row < n) ? row : (n - 1);

    float acc[5] = {0.f, 0.f, 0.f, 0.f, 0.f};
    const float* mrow = M + (size_t)rowc * DIM;
    for (int k = 0; k < DIM; k += 4) {
        float4 a = __ldg((const float4*)(mrow + k));
        #pragma unroll
        for (int t = 0; t < 5; t++) {
            int j = jg * 5 + t;
            acc[t] += a.x * Ws[(k    ) * 40 + j];
            acc[t] += a.y * Ws[(k + 1) * 40 + j];
            acc[t] += a.z * Ws[(k + 2) * 40 + j];
            acc[t] += a.w * Ws[(k + 3) * 40 + j];
        }
    }
    #pragma unroll
    for (int t = 0; t < 5; t++) acc[t] += __ldg(&b[jg * 5 + t]);

    float mx = acc[0];
    #pragma unroll
    for (int t = 1; t < 5; t++) mx = fmaxf(mx, acc[t]);
    #pragma unroll
    for (int o = 1; o < 8; o <<= 1)
        mx = fmaxf(mx, __shfl_xor_sync(0xffffffffu, mx, o));
    float e[5], s = 0.f;
    #pragma unroll
    for (int t = 0; t < 5; t++) { e[t] = expf(acc[t] - mx); s += e[t]; }
    #pragma unroll
    for (int o = 1; o < 8; o <<= 1)
        s += __shfl_xor_sync(0xffffffffu, s, o);
    float inv = 1.f / s;

    if (row < n) {
        #pragma unroll
        for (int t = 0; t < 5; t++) {
            int j = jg * 5 + t;
            logits[(size_t)row * 40 + j] = acc[t];
            probs[(size_t)row * 40 + j]  = e[t] * inv;
        }
    }
}

extern "C" void kernel_launch(void* const* d_in, const int* in_sizes, int n_in,
                              void* d_out, int out_size)
{
    const float* x   = (const float*)d_in[0];
    const int*   ei  = (const int*)d_in[1];
    const float* W1  = (const float*)d_in[2];
    const float* b1  = (const float*)d_in[3];
    const float* W2  = (const float*)d_in[4];
    const float* b2  = (const float*)d_in[5];
    const float* W3  = (const float*)d_in[6];
    const float* b3  = (const float*)d_in[7];
    const float* Wm1 = (const float*)d_in[8];
    const float* bm1 = (const float*)d_in[9];
    const float* Wm2 = (const float*)d_in[10];
    const float* bm2 = (const float*)d_in[11];

    int n = in_sizes[0] / DIM;
    int E = in_sizes[1] / 2;
    const int* src = ei;
    const int* dst = ei + E;

    float* out    = (float*)d_out;
    float* logits = out;
    float* probs  = out + (size_t)n * 40;
    float* emb    = out + (size_t)n * 80;

    float *bufA, *bufB, *Wp;
    cudaGetSymbolAddress((void**)&bufA, g_bufA);
    cudaGetSymbolAddress((void**)&bufB, g_bufB);
    cudaGetSymbolAddress((void**)&Wp,   g_Wp);
    float* Wp1 = Wp;
    float* Wp2 = Wp + 64 * DIM * 2;
    float* Wp3 = Wp + 2 * 64 * DIM * 2;
    float* Wpm = Wp + 3 * 64 * DIM * 2;

    k_zero<<<(n + 255) / 256, 256>>>(n);
    k_hist<<<(E + 255) / 256, 256>>>(dst, E);
    k_scan<<<1, 1024>>>(n, E);
    k_fill<<<(E + 255) / 256, 256>>>(src, dst, E);

    int pw_grid = (64 * DIM + 255) / 256;
    k_packW<<<pw_grid, 256>>>(W1, Wp1);
    k_packW<<<pw_grid, 256>>>(W2, Wp2);
    k_packW<<<pw_grid, 256>>>(W3, Wp3);
    k_packW<<<pw_grid, 256>>>(Wm1, Wpm);

    int gg = (n + 63) / 64;
    int ag = (n + 7) / 8;

    k_gemm<<<gg, 256>>>(x,    Wp1, nullptr, bufA, n, 0);
    k_agg <<<ag, 256>>>(bufA, b1, bufB, n);
    k_gemm<<<gg, 256>>>(bufB, Wp2, nullptr, bufA, n, 0);
    k_agg <<<ag, 256>>>(bufA, b2, bufB, n);
    k_gemm<<<gg, 256>>>(bufB, Wp3, nullptr, bufA, n, 0);
    k_agg <<<ag, 256>>>(bufA, b3, emb, n);

    k_gemm<<<gg, 256>>>(emb,  Wpm, bm1, bufA, n, 1);
    k_mlp2<<<(n + 31) / 32, 256>>>(bufA, Wm2, bm2, logits, probs, n);
}